// round 15
// baseline (speedup 1.0000x reference)
#include <cuda_runtime.h>
#include <cuda_bf16.h>
#include <cuda_fp16.h>
#include <cstdint>
#include <math.h>

#define NSTREAM 2
#define B_ 2
#define N_ 4096
#define C_ 256
#define H_ 8
#define D_ 32
#define M_ 1024
#define ATTN_SCALE 0.17677669529663687f   // 1/sqrt(32)

// ---------------- scratch (static device allocations; no cudaMalloc) -------
__device__ float g_q [NSTREAM * B_ * N_ * C_];          // fp32 q
__device__ float g_xs[NSTREAM * B_ * M_ * C_];          // conv out (fp32)
__device__ float g_kv[NSTREAM * B_ * M_ * 2 * C_];      // fp32 kv
__device__ float g_vcs[4 * 8 * 256];                    // V colsum partials
__device__ __nv_bfloat16 g_xsh[NSTREAM * B_ * M_ * C_]; // ln(xs) hi/lo
__device__ __nv_bfloat16 g_xsl[NSTREAM * B_ * M_ * C_];
__device__ __nv_bfloat16 g_oh [NSTREAM * B_ * N_ * C_]; // attn out hi/lo
__device__ __nv_bfloat16 g_ol [NSTREAM * B_ * N_ * C_];
__device__ __nv_bfloat16 g_wqh[256 * 256],   g_wql[256 * 256];
__device__ __nv_bfloat16 g_wkvh[512 * 256],  g_wkvl[512 * 256];
__device__ __nv_bfloat16 g_wph[256 * 256],   g_wpl[256 * 256];
__device__ __nv_bfloat16 g_wsrh[256 * 1024], g_wsrl[256 * 1024]; // permuted

// ======================= mma / ldmatrix wrappers ===========================
__device__ __forceinline__ void mma_bf16(float* c, const uint32_t* a,
                                         const uint32_t* b) {
    asm volatile(
        "mma.sync.aligned.m16n8k16.row.col.f32.bf16.bf16.f32 "
        "{%0,%1,%2,%3}, {%4,%5,%6,%7}, {%8,%9}, {%0,%1,%2,%3};"
        : "+f"(c[0]), "+f"(c[1]), "+f"(c[2]), "+f"(c[3])
        : "r"(a[0]), "r"(a[1]), "r"(a[2]), "r"(a[3]), "r"(b[0]), "r"(b[1]));
}
__device__ __forceinline__ void mma_f16(float* c, const uint32_t* a,
                                        const uint32_t* b) {
    asm volatile(
        "mma.sync.aligned.m16n8k16.row.col.f32.f16.f16.f32 "
        "{%0,%1,%2,%3}, {%4,%5,%6,%7}, {%8,%9}, {%0,%1,%2,%3};"
        : "+f"(c[0]), "+f"(c[1]), "+f"(c[2]), "+f"(c[3])
        : "r"(a[0]), "r"(a[1]), "r"(a[2]), "r"(a[3]), "r"(b[0]), "r"(b[1]));
}
__device__ __forceinline__ void ldsm4(uint32_t& r0, uint32_t& r1,
                                      uint32_t& r2, uint32_t& r3,
                                      uint32_t addr) {
    asm volatile(
        "ldmatrix.sync.aligned.m8n8.x4.shared.b16 {%0,%1,%2,%3}, [%4];"
        : "=r"(r0), "=r"(r1), "=r"(r2), "=r"(r3) : "r"(addr));
}
__device__ __forceinline__ uint32_t pack_h2(float x, float y) {
    __half2 v = __floats2half2_rn(x, y);
    return *(uint32_t*)&v;
}
__device__ __forceinline__ uint32_t smem_u32(const void* p) {
    uint32_t a;
    asm("{ .reg .u64 t; cvta.to.shared.u64 t, %1; cvt.u32.u64 %0, t; }"
        : "=r"(a) : "l"(p));
    return a;
}

// split 16 fp32 (in 4 float4 regs) -> bf16 hi/lo smem stores
__device__ __forceinline__ void split_store16(const float4* v,
                                              __nv_bfloat16* __restrict__ dh,
                                              __nv_bfloat16* __restrict__ dl)
{
#pragma unroll
    for (int j = 0; j < 4; j++) {
        float4 w = v[j];
        __nv_bfloat16 h0 = __float2bfloat16_rn(w.x);
        __nv_bfloat16 h1 = __float2bfloat16_rn(w.y);
        __nv_bfloat16 h2 = __float2bfloat16_rn(w.z);
        __nv_bfloat16 h3 = __float2bfloat16_rn(w.w);
        __nv_bfloat162 hh0; hh0.x = h0; hh0.y = h1;
        __nv_bfloat162 hh1; hh1.x = h2; hh1.y = h3;
        *(__nv_bfloat162*)(dh + j * 4)     = hh0;
        *(__nv_bfloat162*)(dh + j * 4 + 2) = hh1;
        __nv_bfloat162 ll0, ll1;
        ll0.x = __float2bfloat16_rn(w.x - __bfloat162float(h0));
        ll0.y = __float2bfloat16_rn(w.y - __bfloat162float(h1));
        ll1.x = __float2bfloat16_rn(w.z - __bfloat162float(h2));
        ll1.y = __float2bfloat16_rn(w.w - __bfloat162float(h3));
        *(__nv_bfloat162*)(dl + j * 4)     = ll0;
        *(__nv_bfloat162*)(dl + j * 4 + 2) = ll1;
    }
}

// ======================= conversion kernels ================================
__global__ void cvt_split_kernel(const float* __restrict__ src,
                                 __nv_bfloat16* __restrict__ h,
                                 __nv_bfloat16* __restrict__ l, int n)
{
    int i = blockIdx.x * 256 + threadIdx.x;
    if (i < n) {
        float v = src[i];
        __nv_bfloat16 hi = __float2bfloat16_rn(v);
        h[i] = hi;
        l[i] = __float2bfloat16_rn(v - __bfloat162float(hi));
    }
}

// Wsr [o][c][di][dj] -> permuted [o][q*256+c], split hi/lo
__global__ void wsr_perm_kernel(const float* __restrict__ Wsr,
                                __nv_bfloat16* __restrict__ h,
                                __nv_bfloat16* __restrict__ l)
{
    int idx = blockIdx.x * 256 + threadIdx.x;
    int n = idx >> 10, r = idx & 1023;
    int qq = r >> 8, cc = r & 255;
    float v = Wsr[n * 1024 + cc * 4 + qq];
    __nv_bfloat16 hi = __float2bfloat16_rn(v);
    h[idx] = hi;
    l[idx] = __float2bfloat16_rn(v - __bfloat162float(hi));
}

// V column-sum partials
__global__ void vcs_kernel(const float* __restrict__ kv, float* __restrict__ out)
{
    const int seg = blockIdx.x, sb = blockIdx.y, c = threadIdx.x;
    const float* p = kv + ((long)sb * M_ + seg * 128) * 512 + 256 + c;
    float s0 = 0.f, s1 = 0.f, s2 = 0.f, s3 = 0.f;
#pragma unroll 8
    for (int m = 0; m < 128; m += 4) {
        s0 += p[(long)m * 512];
        s1 += p[(long)(m + 1) * 512];
        s2 += p[(long)(m + 2) * 512];
        s3 += p[(long)(m + 3) * 512];
    }
    out[(sb * 8 + seg) * 256 + c] = (s0 + s1) + (s2 + s3);
}

// ======================= split-bf16 GEMM core ==============================
#define GSTR 40

__device__ __forceinline__ void gemm_tile_compute(
    uint32_t sAh_b, uint32_t sAl_b, uint32_t sWh_b, uint32_t sWl_b,
    float acc[2][4][4], int lane, int wm, int wn)
{
    const int arow = lane & 7, sel = lane >> 3;
    const uint32_t aoff0 = (uint32_t)(2 * ((arow + 8 * (sel & 1)) * GSTR +
                                           8 * (sel >> 1)));
    const uint32_t boff0 = (uint32_t)(2 * ((arow + 8 * (sel >> 1)) * GSTR +
                                           8 * (sel & 1)));
#pragma unroll
    for (int kt = 0; kt < 2; kt++) {
        uint32_t ah[2][4], al[2][4];
#pragma unroll
        for (int mt = 0; mt < 2; mt++) {
            uint32_t off = aoff0 +
                (uint32_t)(2 * ((wm * 32 + mt * 16) * GSTR + kt * 16));
            ldsm4(ah[mt][0], ah[mt][1], ah[mt][2], ah[mt][3], sAh_b + off);
            ldsm4(al[mt][0], al[mt][1], al[mt][2], al[mt][3], sAl_b + off);
        }
        uint32_t bh[4][2], bl[4][2];
#pragma unroll
        for (int np = 0; np < 2; np++) {
            uint32_t off = boff0 +
                (uint32_t)(2 * ((wn * 32 + np * 16) * GSTR + kt * 16));
            ldsm4(bh[np*2][0], bh[np*2][1], bh[np*2+1][0], bh[np*2+1][1],
                  sWh_b + off);
            ldsm4(bl[np*2][0], bl[np*2][1], bl[np*2+1][0], bl[np*2+1][1],
                  sWl_b + off);
        }
#pragma unroll
        for (int nt = 0; nt < 4; nt++)
#pragma unroll
            for (int mt = 0; mt < 2; mt++) {
                mma_bf16(acc[mt][nt], ah[mt], bh[nt]);
                mma_bf16(acc[mt][nt], al[mt], bh[nt]);
                mma_bf16(acc[mt][nt], ah[mt], bl[nt]);
            }
    }
}

__device__ __forceinline__ void gemm_epilogue(
    float acc[2][4][4], const float* bias, float* Cp, int Nc,
    int m0, int n0, int lr, int lc, int wm, int wn)
{
#pragma unroll
    for (int mt = 0; mt < 2; mt++) {
#pragma unroll
        for (int nt = 0; nt < 4; nt++) {
            int row = m0 + wm * 32 + mt * 16 + lr;
            int col = n0 + wn * 32 + nt * 8 + lc;
            float b0 = 0.f, b1 = 0.f;
            if (bias) { b0 = bias[col]; b1 = bias[col + 1]; }
            *(float2*)&Cp[(long)row * Nc + col] =
                make_float2(acc[mt][nt][0] + b0, acc[mt][nt][1] + b1);
            *(float2*)&Cp[(long)(row + 8) * Nc + col] =
                make_float2(acc[mt][nt][2] + b0, acc[mt][nt][3] + b1);
        }
    }
}

// ---- GEMM with pre-split bf16 A (kv proj, out proj); reg-prefetch pipeline
__global__ void __launch_bounds__(256)
gemm_bf16_split(const __nv_bfloat16* __restrict__ Ah,
                const __nv_bfloat16* __restrict__ Al, long astride,
                const __nv_bfloat16* __restrict__ Wh,
                const __nv_bfloat16* __restrict__ Wl,
                const float* __restrict__ bias,
                float* __restrict__ C, long cstride, int Nc, int K)
{
    __shared__ __align__(16) __nv_bfloat16 sAh[128 * GSTR], sAl[128 * GSTR];
    __shared__ __align__(16) __nv_bfloat16 sWh[64 * GSTR],  sWl[64 * GSTR];

    const __nv_bfloat16* Ahp = Ah + (long)blockIdx.z * astride;
    const __nv_bfloat16* Alp = Al + (long)blockIdx.z * astride;
    float* Cp = C + (long)blockIdx.z * cstride;

    const int t = threadIdx.x;
    const int warp = t >> 5, lane = t & 31;
    const int lr = lane >> 2, lc = (lane & 3) * 2;
    const int wm = warp >> 1, wn = warp & 1;
    const int m0 = blockIdx.y * 128, n0 = blockIdx.x * 64;
    const int ar = t >> 1, acb = (t & 1) * 16;
    const int wr = t >> 2, wcb = (t & 3) * 8;
    const uint32_t sAh_b = smem_u32(sAh), sAl_b = smem_u32(sAl);
    const uint32_t sWh_b = smem_u32(sWh), sWl_b = smem_u32(sWl);

    float acc[2][4][4];
#pragma unroll
    for (int i = 0; i < 2; i++)
#pragma unroll
        for (int j = 0; j < 4; j++)
#pragma unroll
            for (int k = 0; k < 4; k++) acc[i][j][k] = 0.f;

    uint4 pah0, pah1, pal0, pal1, pwh, pwl;
    {
        const long ab = (long)(m0 + ar) * K + acb;
        pah0 = *(const uint4*)(Ahp + ab);
        pah1 = *(const uint4*)(Ahp + ab + 8);
        pal0 = *(const uint4*)(Alp + ab);
        pal1 = *(const uint4*)(Alp + ab + 8);
        const long wb = (long)(n0 + wr) * K + wcb;
        pwh = *(const uint4*)(Wh + wb);
        pwl = *(const uint4*)(Wl + wb);
    }

    for (int k0 = 0; k0 < K; k0 += 32) {
        __syncthreads();
        *(uint4*)&sAh[ar * GSTR + acb]     = pah0;
        *(uint4*)&sAh[ar * GSTR + acb + 8] = pah1;
        *(uint4*)&sAl[ar * GSTR + acb]     = pal0;
        *(uint4*)&sAl[ar * GSTR + acb + 8] = pal1;
        *(uint4*)&sWh[wr * GSTR + wcb] = pwh;
        *(uint4*)&sWl[wr * GSTR + wcb] = pwl;
        if (k0 + 32 < K) {
            const long ab = (long)(m0 + ar) * K + k0 + 32 + acb;
            pah0 = *(const uint4*)(Ahp + ab);
            pah1 = *(const uint4*)(Ahp + ab + 8);
            pal0 = *(const uint4*)(Alp + ab);
            pal1 = *(const uint4*)(Alp + ab + 8);
            const long wb = (long)(n0 + wr) * K + k0 + 32 + wcb;
            pwh = *(const uint4*)(Wh + wb);
            pwl = *(const uint4*)(Wl + wb);
        }
        __syncthreads();
        gemm_tile_compute(sAh_b, sAl_b, sWh_b, sWl_b, acc, lane, wm, wn);
    }
    gemm_epilogue(acc, bias, Cp, Nc, m0, n0, lr, lc, wm, wn);
}

// ---- FUSED q-proj + conv kernel (both read fp32 x, inline split) ----------
// grid.x in [0, 320): x < 64 -> conv tile (launched first; 4x longer),
// x >= 64 -> q-proj tile. grid.z = stream.
__global__ void __launch_bounds__(256)
qx_conv_kernel(const float* __restrict__ x0, const float* __restrict__ x1,
               const __nv_bfloat16* __restrict__ Wqh,
               const __nv_bfloat16* __restrict__ Wql,
               const __nv_bfloat16* __restrict__ Wsh,
               const __nv_bfloat16* __restrict__ Wsl,
               const float* __restrict__ bsr,
               float* __restrict__ Cq, float* __restrict__ Cs)
{
    __shared__ __align__(16) __nv_bfloat16 sAh[128 * GSTR], sAl[128 * GSTR];
    __shared__ __align__(16) __nv_bfloat16 sWh[64 * GSTR],  sWl[64 * GSTR];

    const float* xp = blockIdx.z ? x1 : x0;

    const int t = threadIdx.x;
    const int warp = t >> 5, lane = t & 31;
    const int lr = lane >> 2, lc = (lane & 3) * 2;
    const int wm = warp >> 1, wn = warp & 1;
    const int ar = t >> 1, acb = (t & 1) * 16;
    const int wr = t >> 2, wcb = (t & 3) * 8;
    const uint32_t sAh_b = smem_u32(sAh), sAl_b = smem_u32(sAl);
    const uint32_t sWh_b = smem_u32(sWh), sWl_b = smem_u32(sWl);

    float acc[2][4][4];
#pragma unroll
    for (int i = 0; i < 2; i++)
#pragma unroll
        for (int j = 0; j < 4; j++)
#pragma unroll
            for (int k = 0; k < 4; k++) acc[i][j][k] = 0.f;

    if (blockIdx.x < 64) {
        // ================= conv tile =================
        const int bx = blockIdx.x;
        const int m0 = (bx >> 2) * 128, n0 = (bx & 3) * 64;
        float* Cp = Cs + (long)blockIdx.z * (B_ * M_ * C_);

        const int row = m0 + ar;
        const int bidx = row >> 10, mm = row & 1023;
        const int pi = mm >> 5, pj = mm & 31;
        long pix[4];
#pragma unroll
        for (int qq = 0; qq < 4; qq++)
            pix[qq] = (long)bidx * (N_ * C_) +
                      (long)(((2 * pi + (qq >> 1)) * 64) + 2 * pj + (qq & 1)) * C_;

        float4 pa[4];
        uint4 pwh, pwl;
        {
            const float* src = xp + pix[0] + acb;
#pragma unroll
            for (int j = 0; j < 4; j++) pa[j] = *(const float4*)(src + j * 4);
            const long wb = (long)(n0 + wr) * 1024 + wcb;
            pwh = *(const uint4*)(Wsh + wb);
            pwl = *(const uint4*)(Wsl + wb);
        }

        for (int k0 = 0; k0 < 1024; k0 += 32) {
            __syncthreads();
            split_store16(pa, &sAh[ar * GSTR + acb], &sAl[ar * GSTR + acb]);
            *(uint4*)&sWh[wr * GSTR + wcb] = pwh;
            *(uint4*)&sWl[wr * GSTR + wcb] = pwl;
            if (k0 + 32 < 1024) {
                const int kn = k0 + 32;
                const float* src = xp + pix[kn >> 8] + (kn & 255) + acb;
#pragma unroll
                for (int j = 0; j < 4; j++) pa[j] = *(const float4*)(src + j * 4);
                const long wb = (long)(n0 + wr) * 1024 + kn + wcb;
                pwh = *(const uint4*)(Wsh + wb);
                pwl = *(const uint4*)(Wsl + wb);
            }
            __syncthreads();
            gemm_tile_compute(sAh_b, sAl_b, sWh_b, sWl_b, acc, lane, wm, wn);
        }
        gemm_epilogue(acc, bsr, Cp, 256, m0, n0, lr, lc, wm, wn);
    } else {
        // ================= q-proj tile =================
        const int bx = blockIdx.x - 64;
        const int m0 = (bx >> 2) * 128, n0 = (bx & 3) * 64;
        float* Cp = Cq + (long)blockIdx.z * ((long)B_ * N_ * C_);

        float4 pa[4];
        uint4 pwh, pwl;
        {
            const float* src = xp + (long)(m0 + ar) * 256 + acb;
#pragma unroll
            for (int j = 0; j < 4; j++) pa[j] = *(const float4*)(src + j * 4);
            const long wb = (long)(n0 + wr) * 256 + wcb;
            pwh = *(const uint4*)(Wqh + wb);
            pwl = *(const uint4*)(Wql + wb);
        }

        for (int k0 = 0; k0 < 256; k0 += 32) {
            __syncthreads();
            split_store16(pa, &sAh[ar * GSTR + acb], &sAl[ar * GSTR + acb]);
            *(uint4*)&sWh[wr * GSTR + wcb] = pwh;
            *(uint4*)&sWl[wr * GSTR + wcb] = pwl;
            if (k0 + 32 < 256) {
                const float* src = xp + (long)(m0 + ar) * 256 + k0 + 32 + acb;
#pragma unroll
                for (int j = 0; j < 4; j++) pa[j] = *(const float4*)(src + j * 4);
                const long wb = (long)(n0 + wr) * 256 + k0 + 32 + wcb;
                pwh = *(const uint4*)(Wqh + wb);
                pwl = *(const uint4*)(Wql + wb);
            }
            __syncthreads();
            gemm_tile_compute(sAh_b, sAl_b, sWh_b, sWl_b, acc, lane, wm, wn);
        }
        gemm_epilogue(acc, nullptr, Cp, 256, m0, n0, lr, lc, wm, wn);
    }
}

// ---------------------------------------------------------------------------
// LayerNorm over C=256, writes bf16 hi/lo.
// ---------------------------------------------------------------------------
__global__ void __launch_bounds__(256)
ln_kernel(const float* __restrict__ xs,
          __nv_bfloat16* __restrict__ outh, __nv_bfloat16* __restrict__ outl,
          const float* __restrict__ w0, const float* __restrict__ b0,
          const float* __restrict__ w1, const float* __restrict__ b1)
{
    __shared__ float red[8];
    const int row = blockIdx.x;
    const int s = row >> 11;
    const float* w  = s ? w1 : w0;
    const float* bb = s ? b1 : b0;
    const float* p = xs + (long)row * C_;
    const int t = threadIdx.x;

    const float v = p[t];
    float x = v;
#pragma unroll
    for (int o = 16; o; o >>= 1) x += __shfl_xor_sync(0xffffffffu, x, o);
    if ((t & 31) == 0) red[t >> 5] = x;
    __syncthreads();
    float mu = 0.f;
#pragma unroll
    for (int i = 0; i < 8; i++) mu += red[i];
    mu *= (1.f / 256.f);
    __syncthreads();

    const float dv = v - mu;
    float sq = dv * dv;
#pragma unroll
    for (int o = 16; o; o >>= 1) sq += __shfl_xor_sync(0xffffffffu, sq, o);
    if ((t & 31) == 0) red[t >> 5] = sq;
    __syncthreads();
    float var = 0.f;
#pragma unroll
    for (int i = 0; i < 8; i++) var += red[i];
    var *= (1.f / 256.f);

    float y = dv * rsqrtf(var + 1e-5f) * w[t] + bb[t];
    __nv_bfloat16 hi = __float2bfloat16_rn(y);
    outh[(long)row * C_ + t] = hi;
    outl[(long)row * C_ + t] = __float2bfloat16_rn(y - __bfloat162float(hi));
}

// ---------------------------------------------------------------------------
// fp16 mma attention, centered softmax, ldmatrix frags, MMA-based row sums.
//   P' = exp(s) - 1 ;  out = (colsum_V + P' V) / (1024 + sum P')
// Row sums computed by an extra mma against an all-ones fp16 B fragment:
// every output column equals the row sum, so no shuffle reduce is needed.
// ---------------------------------------------------------------------------
#define KSTR 40   // fp16 row stride (32 + 8)
#define VSTR 72   // fp16 row stride (64 + 8)

__global__ void __launch_bounds__(256)
attn_f16_kernel(const float* __restrict__ q, const float* __restrict__ kv,
                const float* __restrict__ vcs,
                __nv_bfloat16* __restrict__ oh, __nv_bfloat16* __restrict__ ol)
{
    __shared__ __align__(16) __half qs[128 * KSTR];
    __shared__ __align__(16) __half ks[64 * KSTR];
    __shared__ __align__(16) __half vt[32 * VSTR];

    const int t = threadIdx.x;
    const int warp = t >> 5, lane = t & 31;
    const int lr = lane >> 2, lc = (lane & 3) * 2;
    const int arow = lane & 7, sel = lane >> 3;
    const int qrow0 = warp * 16;
    const uint32_t ks_b = smem_u32(ks), vt_b = smem_u32(vt);
    const uint32_t kboff = (uint32_t)(2 * ((arow + 8 * (sel >> 1)) * KSTR +
                                           8 * (sel & 1)));
    const uint32_t vboff = (uint32_t)(2 * ((arow + 8 * (sel >> 1)) * VSTR +
                                           8 * (sel & 1)));

    const int qt = blockIdx.x, bhid = blockIdx.y, s = blockIdx.z;
    const int h = bhid & 7;
    const long sb = (long)(s * 2 + (bhid >> 3));
    const float* qg  = q  + (sb * N_ + (long)qt * 128) * C_ + h * 32;
    const float* kvg = kv + sb * M_ * 512;

    // ---- stage Q (fp16, scaled) ----
#pragma unroll
    for (int i = 0; i < 16; i++) {
        int flat = t + i * 256;
        int rr = flat >> 5, d = flat & 31;
        qs[rr * KSTR + d] = __float2half_rn(qg[(long)rr * C_ + d] * ATTN_SCALE);
    }
    __syncthreads();

    uint32_t aQ[2][4];
#pragma unroll
    for (int kt = 0; kt < 2; kt++) {
        aQ[kt][0] = *(const uint32_t*)&qs[(qrow0 + lr) * KSTR + kt * 16 + lc];
        aQ[kt][1] = *(const uint32_t*)&qs[(qrow0 + lr + 8) * KSTR + kt * 16 + lc];
        aQ[kt][2] = *(const uint32_t*)&qs[(qrow0 + lr) * KSTR + kt * 16 + lc + 8];
        aQ[kt][3] = *(const uint32_t*)&qs[(qrow0 + lr + 8) * KSTR + kt * 16 + lc + 8];
    }

    float oacc[4][4];
#pragma unroll
    for (int i = 0; i < 4; i++)
#pragma unroll
        for (int j = 0; j < 4; j++) oacc[i][j] = 0.f;
    float sums[4] = {0.f, 0.f, 0.f, 0.f};
    const uint32_t bOnes[2] = {0x3C003C00u, 0x3C003C00u};  // fp16 1.0 x4

    // ---- prefetch chunk 0 into regs ----
    float pk[8], pv[8];
    {
        const float* kg = kvg + h * 32;
#pragma unroll
        for (int i = 0; i < 8; i++) {
            int flat = t + i * 256;
            int key = flat >> 5, d = flat & 31;
            pk[i] = kg[(long)key * 512 + d];
            pv[i] = kg[(long)key * 512 + 256 + d];
        }
    }

    for (int c = 0; c < 16; c++) {
        __syncthreads();
#pragma unroll
        for (int i = 0; i < 8; i++) {
            int flat = t + i * 256;
            int key = flat >> 5, d = flat & 31;
            ks[key * KSTR + d] = __float2half_rn(pk[i]);
            vt[d * VSTR + key] = __float2half_rn(pv[i]);
        }
        if (c < 15) {
            const float* kg = kvg + (long)((c + 1) * 64) * 512 + h * 32;
#pragma unroll
            for (int i = 0; i < 8; i++) {
                int flat = t + i * 256;
                int key = flat >> 5, d = flat & 31;
                pk[i] = kg[(long)key * 512 + d];
                pv[i] = kg[(long)key * 512 + 256 + d];
            }
        }
        __syncthreads();

        // ---- S = Q K^T (B frags via ldmatrix) ----
        float sc[8][4];
#pragma unroll
        for (int nt = 0; nt < 8; nt++)
            sc[nt][0] = sc[nt][1] = sc[nt][2] = sc[nt][3] = 0.f;
#pragma unroll
        for (int kt = 0; kt < 2; kt++) {
            uint32_t bK[8][2];
#pragma unroll
            for (int np = 0; np < 4; np++) {
                uint32_t off = kboff +
                    (uint32_t)(2 * ((np * 16) * KSTR + kt * 16));
                ldsm4(bK[np*2][0], bK[np*2][1], bK[np*2+1][0], bK[np*2+1][1],
                      ks_b + off);
            }
#pragma unroll
            for (int nt = 0; nt < 8; nt++)
                mma_f16(sc[nt], aQ[kt], bK[nt]);
        }

        // ---- P' = exp(S) - 1 ----
#pragma unroll
        for (int nt = 0; nt < 8; nt++) {
            sc[nt][0] = __expf(sc[nt][0]) - 1.f;
            sc[nt][1] = __expf(sc[nt][1]) - 1.f;
            sc[nt][2] = __expf(sc[nt][2]) - 1.f;
            sc[nt][3] = __expf(sc[nt][3]) - 1.f;
        }

        // ---- O += P' V ; row sums += P' * ones ----
#pragma unroll
        for (int kt = 0; kt < 4; kt++) {
            uint32_t aP[4];
            aP[0] = pack_h2(sc[kt * 2][0], sc[kt * 2][1]);
            aP[1] = pack_h2(sc[kt * 2][2], sc[kt * 2][3]);
            aP[2] = pack_h2(sc[kt * 2 + 1][0], sc[kt * 2 + 1][1]);
            aP[3] = pack_h2(sc[kt * 2 + 1][2], sc[kt * 2 + 1][3]);
            mma_f16(sums, aP, bOnes);
            uint32_t bV[4][2];
#pragma unroll
            for (int np = 0; np < 2; np++) {
                uint32_t off = vboff +
                    (uint32_t)(2 * ((np * 16) * VSTR + kt * 16));
                ldsm4(bV[np*2][0], bV[np*2][1], bV[np*2+1][0], bV[np*2+1][1],
                      vt_b + off);
            }
#pragma unroll
            for (int nt = 0; nt < 4; nt++)
                mma_f16(oacc[nt], aP, bV[nt]);
        }
    }

    // ---- finalize (sums[0]/sums[2] hold full row sums; all lanes agree) ----
    const float inv0 = 1.f / (1024.f + sums[0]);
    const float inv1 = 1.f / (1024.f + sums[2]);

    const long obase = (sb * N_ + (long)qt * 128 + qrow0) * C_ + h * 32;
#pragma unroll
    for (int nt = 0; nt < 4; nt++) {
        const int col = nt * 8 + lc;
        float cs0 = 0.f, cs1 = 0.f;
#pragma unroll
        for (int seg = 0; seg < 8; seg++) {
            cs0 += vcs[(sb * 8 + seg) * 256 + h * 32 + col];
            cs1 += vcs[(sb * 8 + seg) * 256 + h * 32 + col + 1];
        }
        float o00 = (cs0 + oacc[nt][0]) * inv0;
        float o01 = (cs1 + oacc[nt][1]) * inv0;
        float o10 = (cs0 + oacc[nt][2]) * inv1;
        float o11 = (cs1 + oacc[nt][3]) * inv1;
        long i0 = obase + (long)lr * C_ + col;
        long i1 = obase + (long)(lr + 8) * C_ + col;
        __nv_bfloat16 h00 = __float2bfloat16_rn(o00);
        __nv_bfloat16 h01 = __float2bfloat16_rn(o01);
        __nv_bfloat16 h10 = __float2bfloat16_rn(o10);
        __nv_bfloat16 h11 = __float2bfloat16_rn(o11);
        oh[i0] = h00; oh[i0 + 1] = h01;
        oh[i1] = h10; oh[i1 + 1] = h11;
        ol[i0]     = __float2bfloat16_rn(o00 - __bfloat162float(h00));
        ol[i0 + 1] = __float2bfloat16_rn(o01 - __bfloat162float(h01));
        ol[i1]     = __float2bfloat16_rn(o10 - __bfloat162float(h10));
        ol[i1 + 1] = __float2bfloat16_rn(o11 - __bfloat162float(h11));
    }
}

// ---------------------------------------------------------------------------
extern "C" void kernel_launch(void* const* d_in, const int* in_sizes, int n_in,
                              void* d_out, int out_size)
{
    const float* x0    = (const float*)d_in[0];
    const float* x1    = (const float*)d_in[1];
    const float* Wq    = (const float*)d_in[2];
    const float* Wkv   = (const float*)d_in[3];
    const float* Wproj = (const float*)d_in[4];
    const float* bproj = (const float*)d_in[5];
    const float* Wsr   = (const float*)d_in[6];
    const float* bsr   = (const float*)d_in[7];
    const float* lw0   = (const float*)d_in[8];
    const float* lb0   = (const float*)d_in[9];
    const float* lw1   = (const float*)d_in[10];
    const float* lb1   = (const float*)d_in[11];
    float* out = (float*)d_out;

    float *qp, *xsp, *kvp, *vcsp;
    __nv_bfloat16 *xsh, *xsl, *ohp, *olp;
    __nv_bfloat16 *wqh, *wql, *wkvh, *wkvl, *wph, *wpl, *wsrh, *wsrl;
    cudaGetSymbolAddress((void**)&qp,   g_q);
    cudaGetSymbolAddress((void**)&xsp,  g_xs);
    cudaGetSymbolAddress((void**)&kvp,  g_kv);
    cudaGetSymbolAddress((void**)&vcsp, g_vcs);
    cudaGetSymbolAddress((void**)&xsh,  g_xsh);
    cudaGetSymbolAddress((void**)&xsl,  g_xsl);
    cudaGetSymbolAddress((void**)&ohp,  g_oh);
    cudaGetSymbolAddress((void**)&olp,  g_ol);
    cudaGetSymbolAddress((void**)&wqh,  g_wqh);
    cudaGetSymbolAddress((void**)&wql,  g_wql);
    cudaGetSymbolAddress((void**)&wkvh, g_wkvh);
    cudaGetSymbolAddress((void**)&wkvl, g_wkvl);
    cudaGetSymbolAddress((void**)&wph,  g_wph);
    cudaGetSymbolAddress((void**)&wpl,  g_wpl);
    cudaGetSymbolAddress((void**)&wsrh, g_wsrh);
    cudaGetSymbolAddress((void**)&wsrl, g_wsrl);

    const long XSTR_ = (long)B_ * N_ * C_;   // 2,097,152
    const long SSTR_ = (long)B_ * M_ * C_;   // 524,288

    // 0) weight conversions (small)
    cvt_split_kernel<<<256, 256>>>(Wq, wqh, wql, 256 * 256);
    cvt_split_kernel<<<512, 256>>>(Wkv, wkvh, wkvl, 512 * 256);
    cvt_split_kernel<<<256, 256>>>(Wproj, wph, wpl, 256 * 256);
    wsr_perm_kernel<<<1024, 256>>>(Wsr, wsrh, wsrl);

    // 1+2) fused: conv tiles (x<64) + q-proj tiles (x>=64)
    qx_conv_kernel<<<dim3(320, 1, 2), 256>>>(x0, x1, wqh, wql,
                                             wsrh, wsrl, bsr, qp, xsp);
    // 3) layernorm -> bf16 hi/lo
    ln_kernel<<<NSTREAM * B_ * M_, 256>>>(xsp, xsh, xsl, lw0, lb0, lw1, lb1);
    // 4) kv = ln(xs) @ Wkv^T (pipelined)
    gemm_bf16_split<<<dim3(8, 16, 2), 256>>>(xsh, xsl, SSTR_, wkvh, wkvl,
                                             nullptr, kvp,
                                             (long)B_ * M_ * 2 * C_, 512, 256);
    // 5) V column sums
    vcs_kernel<<<dim3(8, 4), 256>>>(kvp, vcsp);
    // 6) fp16 attention -> bf16 hi/lo
    attn_f16_kernel<<<dim3(32, 16, 2), 256>>>(qp, kvp, vcsp, ohp, olp);
    // 7) out = attn @ Wproj^T + bproj (pipelined)
    gemm_bf16_split<<<dim3(4, 64, 2), 256>>>(ohp, olp, XSTR_, wph, wpl,
                                             bproj, out, XSTR_, 256, 256);
}

// round 16
// speedup vs baseline: 1.5013x; 1.5013x over previous
#include <cuda_runtime.h>
#include <cuda_bf16.h>
#include <cuda_fp16.h>
#include <cstdint>
#include <math.h>

#define NSTREAM 2
#define B_ 2
#define N_ 4096
#define C_ 256
#define H_ 8
#define D_ 32
#define M_ 1024
#define ATTN_SCALE 0.17677669529663687f   // 1/sqrt(32)

// ---------------- scratch (static device allocations; no cudaMalloc) -------
__device__ float g_q [NSTREAM * B_ * N_ * C_];          // fp32 q
__device__ float g_xs[NSTREAM * B_ * M_ * C_];          // conv out (fp32)
__device__ float g_kv[NSTREAM * B_ * M_ * 2 * C_];      // fp32 kv
__device__ float g_vcs[4 * 8 * 256];                    // V colsum partials
__device__ __nv_bfloat16 g_xsh[NSTREAM * B_ * M_ * C_]; // ln(xs) hi/lo
__device__ __nv_bfloat16 g_xsl[NSTREAM * B_ * M_ * C_];
__device__ __nv_bfloat16 g_oh [NSTREAM * B_ * N_ * C_]; // attn out hi/lo
__device__ __nv_bfloat16 g_ol [NSTREAM * B_ * N_ * C_];
__device__ __nv_bfloat16 g_wqh[256 * 256],   g_wql[256 * 256];
__device__ __nv_bfloat16 g_wkvh[512 * 256],  g_wkvl[512 * 256];
__device__ __nv_bfloat16 g_wph[256 * 256],   g_wpl[256 * 256];
__device__ __nv_bfloat16 g_wsrh[256 * 1024], g_wsrl[256 * 1024]; // permuted

// ======================= mma / ldmatrix wrappers ===========================
__device__ __forceinline__ void mma_bf16(float* c, const uint32_t* a,
                                         const uint32_t* b) {
    asm volatile(
        "mma.sync.aligned.m16n8k16.row.col.f32.bf16.bf16.f32 "
        "{%0,%1,%2,%3}, {%4,%5,%6,%7}, {%8,%9}, {%0,%1,%2,%3};"
        : "+f"(c[0]), "+f"(c[1]), "+f"(c[2]), "+f"(c[3])
        : "r"(a[0]), "r"(a[1]), "r"(a[2]), "r"(a[3]), "r"(b[0]), "r"(b[1]));
}
__device__ __forceinline__ void mma_f16(float* c, const uint32_t* a,
                                        const uint32_t* b) {
    asm volatile(
        "mma.sync.aligned.m16n8k16.row.col.f32.f16.f16.f32 "
        "{%0,%1,%2,%3}, {%4,%5,%6,%7}, {%8,%9}, {%0,%1,%2,%3};"
        : "+f"(c[0]), "+f"(c[1]), "+f"(c[2]), "+f"(c[3])
        : "r"(a[0]), "r"(a[1]), "r"(a[2]), "r"(a[3]), "r"(b[0]), "r"(b[1]));
}
__device__ __forceinline__ void ldsm4(uint32_t& r0, uint32_t& r1,
                                      uint32_t& r2, uint32_t& r3,
                                      uint32_t addr) {
    asm volatile(
        "ldmatrix.sync.aligned.m8n8.x4.shared.b16 {%0,%1,%2,%3}, [%4];"
        : "=r"(r0), "=r"(r1), "=r"(r2), "=r"(r3) : "r"(addr));
}
__device__ __forceinline__ uint32_t pack_h2(float x, float y) {
    __half2 v = __floats2half2_rn(x, y);
    return *(uint32_t*)&v;
}
__device__ __forceinline__ uint32_t smem_u32(const void* p) {
    uint32_t a;
    asm("{ .reg .u64 t; cvta.to.shared.u64 t, %1; cvt.u32.u64 %0, t; }"
        : "=r"(a) : "l"(p));
    return a;
}

// split 16 fp32 (in 4 float4 regs) -> bf16 hi/lo smem stores
__device__ __forceinline__ void split_store16(const float4* v,
                                              __nv_bfloat16* __restrict__ dh,
                                              __nv_bfloat16* __restrict__ dl)
{
#pragma unroll
    for (int j = 0; j < 4; j++) {
        float4 w = v[j];
        __nv_bfloat16 h0 = __float2bfloat16_rn(w.x);
        __nv_bfloat16 h1 = __float2bfloat16_rn(w.y);
        __nv_bfloat16 h2 = __float2bfloat16_rn(w.z);
        __nv_bfloat16 h3 = __float2bfloat16_rn(w.w);
        __nv_bfloat162 hh0; hh0.x = h0; hh0.y = h1;
        __nv_bfloat162 hh1; hh1.x = h2; hh1.y = h3;
        *(__nv_bfloat162*)(dh + j * 4)     = hh0;
        *(__nv_bfloat162*)(dh + j * 4 + 2) = hh1;
        __nv_bfloat162 ll0, ll1;
        ll0.x = __float2bfloat16_rn(w.x - __bfloat162float(h0));
        ll0.y = __float2bfloat16_rn(w.y - __bfloat162float(h1));
        ll1.x = __float2bfloat16_rn(w.z - __bfloat162float(h2));
        ll1.y = __float2bfloat16_rn(w.w - __bfloat162float(h3));
        *(__nv_bfloat162*)(dl + j * 4)     = ll0;
        *(__nv_bfloat162*)(dl + j * 4 + 2) = ll1;
    }
}

// ======================= conversion kernels ================================
__global__ void cvt_split_kernel(const float* __restrict__ src,
                                 __nv_bfloat16* __restrict__ h,
                                 __nv_bfloat16* __restrict__ l, int n)
{
    int i = blockIdx.x * 256 + threadIdx.x;
    if (i < n) {
        float v = src[i];
        __nv_bfloat16 hi = __float2bfloat16_rn(v);
        h[i] = hi;
        l[i] = __float2bfloat16_rn(v - __bfloat162float(hi));
    }
}

// Wsr [o][c][di][dj] -> permuted [o][q*256+c], split hi/lo
__global__ void wsr_perm_kernel(const float* __restrict__ Wsr,
                                __nv_bfloat16* __restrict__ h,
                                __nv_bfloat16* __restrict__ l)
{
    int idx = blockIdx.x * 256 + threadIdx.x;
    int n = idx >> 10, r = idx & 1023;
    int qq = r >> 8, cc = r & 255;
    float v = Wsr[n * 1024 + cc * 4 + qq];
    __nv_bfloat16 hi = __float2bfloat16_rn(v);
    h[idx] = hi;
    l[idx] = __float2bfloat16_rn(v - __bfloat162float(hi));
}

// V column-sum partials
__global__ void vcs_kernel(const float* __restrict__ kv, float* __restrict__ out)
{
    const int seg = blockIdx.x, sb = blockIdx.y, c = threadIdx.x;
    const float* p = kv + ((long)sb * M_ + seg * 128) * 512 + 256 + c;
    float s0 = 0.f, s1 = 0.f, s2 = 0.f, s3 = 0.f;
#pragma unroll 8
    for (int m = 0; m < 128; m += 4) {
        s0 += p[(long)m * 512];
        s1 += p[(long)(m + 1) * 512];
        s2 += p[(long)(m + 2) * 512];
        s3 += p[(long)(m + 3) * 512];
    }
    out[(sb * 8 + seg) * 256 + c] = (s0 + s1) + (s2 + s3);
}

// ======================= split-bf16 GEMM core ==============================
#define GSTR 40

__device__ __forceinline__ void gemm_tile_compute(
    uint32_t sAh_b, uint32_t sAl_b, uint32_t sWh_b, uint32_t sWl_b,
    float acc[2][4][4], int lane, int wm, int wn)
{
    const int arow = lane & 7, sel = lane >> 3;
    const uint32_t aoff0 = (uint32_t)(2 * ((arow + 8 * (sel & 1)) * GSTR +
                                           8 * (sel >> 1)));
    const uint32_t boff0 = (uint32_t)(2 * ((arow + 8 * (sel >> 1)) * GSTR +
                                           8 * (sel & 1)));
#pragma unroll
    for (int kt = 0; kt < 2; kt++) {
        uint32_t ah[2][4], al[2][4];
#pragma unroll
        for (int mt = 0; mt < 2; mt++) {
            uint32_t off = aoff0 +
                (uint32_t)(2 * ((wm * 32 + mt * 16) * GSTR + kt * 16));
            ldsm4(ah[mt][0], ah[mt][1], ah[mt][2], ah[mt][3], sAh_b + off);
            ldsm4(al[mt][0], al[mt][1], al[mt][2], al[mt][3], sAl_b + off);
        }
        uint32_t bh[4][2], bl[4][2];
#pragma unroll
        for (int np = 0; np < 2; np++) {
            uint32_t off = boff0 +
                (uint32_t)(2 * ((wn * 32 + np * 16) * GSTR + kt * 16));
            ldsm4(bh[np*2][0], bh[np*2][1], bh[np*2+1][0], bh[np*2+1][1],
                  sWh_b + off);
            ldsm4(bl[np*2][0], bl[np*2][1], bl[np*2+1][0], bl[np*2+1][1],
                  sWl_b + off);
        }
#pragma unroll
        for (int nt = 0; nt < 4; nt++)
#pragma unroll
            for (int mt = 0; mt < 2; mt++) {
                mma_bf16(acc[mt][nt], ah[mt], bh[nt]);
                mma_bf16(acc[mt][nt], al[mt], bh[nt]);
                mma_bf16(acc[mt][nt], ah[mt], bl[nt]);
            }
    }
}

__device__ __forceinline__ void gemm_epilogue(
    float acc[2][4][4], const float* bias, float* Cp, int Nc,
    int m0, int n0, int lr, int lc, int wm, int wn)
{
#pragma unroll
    for (int mt = 0; mt < 2; mt++) {
#pragma unroll
        for (int nt = 0; nt < 4; nt++) {
            int row = m0 + wm * 32 + mt * 16 + lr;
            int col = n0 + wn * 32 + nt * 8 + lc;
            float b0 = 0.f, b1 = 0.f;
            if (bias) { b0 = bias[col]; b1 = bias[col + 1]; }
            *(float2*)&Cp[(long)row * Nc + col] =
                make_float2(acc[mt][nt][0] + b0, acc[mt][nt][1] + b1);
            *(float2*)&Cp[(long)(row + 8) * Nc + col] =
                make_float2(acc[mt][nt][2] + b0, acc[mt][nt][3] + b1);
        }
    }
}

// ---- GEMM with pre-split bf16 A (kv proj, out proj); reg-prefetch pipeline
__global__ void __launch_bounds__(256)
gemm_bf16_split(const __nv_bfloat16* __restrict__ Ah,
                const __nv_bfloat16* __restrict__ Al, long astride,
                const __nv_bfloat16* __restrict__ Wh,
                const __nv_bfloat16* __restrict__ Wl,
                const float* __restrict__ bias,
                float* __restrict__ C, long cstride, int Nc, int K)
{
    __shared__ __align__(16) __nv_bfloat16 sAh[128 * GSTR], sAl[128 * GSTR];
    __shared__ __align__(16) __nv_bfloat16 sWh[64 * GSTR],  sWl[64 * GSTR];

    const __nv_bfloat16* Ahp = Ah + (long)blockIdx.z * astride;
    const __nv_bfloat16* Alp = Al + (long)blockIdx.z * astride;
    float* Cp = C + (long)blockIdx.z * cstride;

    const int t = threadIdx.x;
    const int warp = t >> 5, lane = t & 31;
    const int lr = lane >> 2, lc = (lane & 3) * 2;
    const int wm = warp >> 1, wn = warp & 1;
    const int m0 = blockIdx.y * 128, n0 = blockIdx.x * 64;
    const int ar = t >> 1, acb = (t & 1) * 16;
    const int wr = t >> 2, wcb = (t & 3) * 8;
    const uint32_t sAh_b = smem_u32(sAh), sAl_b = smem_u32(sAl);
    const uint32_t sWh_b = smem_u32(sWh), sWl_b = smem_u32(sWl);

    float acc[2][4][4];
#pragma unroll
    for (int i = 0; i < 2; i++)
#pragma unroll
        for (int j = 0; j < 4; j++)
#pragma unroll
            for (int k = 0; k < 4; k++) acc[i][j][k] = 0.f;

    uint4 pah0, pah1, pal0, pal1, pwh, pwl;
    {
        const long ab = (long)(m0 + ar) * K + acb;
        pah0 = *(const uint4*)(Ahp + ab);
        pah1 = *(const uint4*)(Ahp + ab + 8);
        pal0 = *(const uint4*)(Alp + ab);
        pal1 = *(const uint4*)(Alp + ab + 8);
        const long wb = (long)(n0 + wr) * K + wcb;
        pwh = *(const uint4*)(Wh + wb);
        pwl = *(const uint4*)(Wl + wb);
    }

    for (int k0 = 0; k0 < K; k0 += 32) {
        __syncthreads();
        *(uint4*)&sAh[ar * GSTR + acb]     = pah0;
        *(uint4*)&sAh[ar * GSTR + acb + 8] = pah1;
        *(uint4*)&sAl[ar * GSTR + acb]     = pal0;
        *(uint4*)&sAl[ar * GSTR + acb + 8] = pal1;
        *(uint4*)&sWh[wr * GSTR + wcb] = pwh;
        *(uint4*)&sWl[wr * GSTR + wcb] = pwl;
        if (k0 + 32 < K) {
            const long ab = (long)(m0 + ar) * K + k0 + 32 + acb;
            pah0 = *(const uint4*)(Ahp + ab);
            pah1 = *(const uint4*)(Ahp + ab + 8);
            pal0 = *(const uint4*)(Alp + ab);
            pal1 = *(const uint4*)(Alp + ab + 8);
            const long wb = (long)(n0 + wr) * K + k0 + 32 + wcb;
            pwh = *(const uint4*)(Wh + wb);
            pwl = *(const uint4*)(Wl + wb);
        }
        __syncthreads();
        gemm_tile_compute(sAh_b, sAl_b, sWh_b, sWl_b, acc, lane, wm, wn);
    }
    gemm_epilogue(acc, bias, Cp, Nc, m0, n0, lr, lc, wm, wn);
}

// ---- GEMM reading fp32 A (inline split): q projection; reg-prefetch -------
__global__ void __launch_bounds__(256)
gemm_x_kernel(const float* __restrict__ A0, const float* __restrict__ A1,
              const __nv_bfloat16* __restrict__ Wh,
              const __nv_bfloat16* __restrict__ Wl,
              float* __restrict__ C)
{
    __shared__ __align__(16) __nv_bfloat16 sAh[128 * GSTR], sAl[128 * GSTR];
    __shared__ __align__(16) __nv_bfloat16 sWh[64 * GSTR],  sWl[64 * GSTR];

    const float* Ap = blockIdx.z ? A1 : A0;
    float* Cp = C + (long)blockIdx.z * ((long)B_ * N_ * C_);

    const int t = threadIdx.x;
    const int warp = t >> 5, lane = t & 31;
    const int lr = lane >> 2, lc = (lane & 3) * 2;
    const int wm = warp >> 1, wn = warp & 1;
    const int m0 = blockIdx.y * 128, n0 = blockIdx.x * 64;
    const int ar = t >> 1, acb = (t & 1) * 16;
    const int wr = t >> 2, wcb = (t & 3) * 8;
    const uint32_t sAh_b = smem_u32(sAh), sAl_b = smem_u32(sAl);
    const uint32_t sWh_b = smem_u32(sWh), sWl_b = smem_u32(sWl);

    float acc[2][4][4];
#pragma unroll
    for (int i = 0; i < 2; i++)
#pragma unroll
        for (int j = 0; j < 4; j++)
#pragma unroll
            for (int k = 0; k < 4; k++) acc[i][j][k] = 0.f;

    float4 pa[4];
    uint4 pwh, pwl;
    {
        const float* src = Ap + (long)(m0 + ar) * 256 + acb;
#pragma unroll
        for (int j = 0; j < 4; j++) pa[j] = *(const float4*)(src + j * 4);
        const long wb = (long)(n0 + wr) * 256 + wcb;
        pwh = *(const uint4*)(Wh + wb);
        pwl = *(const uint4*)(Wl + wb);
    }

    for (int k0 = 0; k0 < 256; k0 += 32) {
        __syncthreads();
        split_store16(pa, &sAh[ar * GSTR + acb], &sAl[ar * GSTR + acb]);
        *(uint4*)&sWh[wr * GSTR + wcb] = pwh;
        *(uint4*)&sWl[wr * GSTR + wcb] = pwl;
        if (k0 + 32 < 256) {
            const float* src = Ap + (long)(m0 + ar) * 256 + k0 + 32 + acb;
#pragma unroll
            for (int j = 0; j < 4; j++) pa[j] = *(const float4*)(src + j * 4);
            const long wb = (long)(n0 + wr) * 256 + k0 + 32 + wcb;
            pwh = *(const uint4*)(Wh + wb);
            pwl = *(const uint4*)(Wl + wb);
        }
        __syncthreads();
        gemm_tile_compute(sAh_b, sAl_b, sWh_b, sWl_b, acc, lane, wm, wn);
    }
    gemm_epilogue(acc, nullptr, Cp, 256, m0, n0, lr, lc, wm, wn);
}

// ---- conv (k=s=2) gather-GEMM, fp32 x inline split; reg-prefetch ----------
__global__ void __launch_bounds__(256)
conv_split_f32(const float* __restrict__ x0, const float* __restrict__ x1,
               const __nv_bfloat16* __restrict__ Wh,
               const __nv_bfloat16* __restrict__ Wl,
               const float* __restrict__ bias, float* __restrict__ C)
{
    __shared__ __align__(16) __nv_bfloat16 sAh[128 * GSTR], sAl[128 * GSTR];
    __shared__ __align__(16) __nv_bfloat16 sWh[64 * GSTR],  sWl[64 * GSTR];

    const float* xp = blockIdx.z ? x1 : x0;
    float* Cp = C + (long)blockIdx.z * (B_ * M_ * C_);

    const int t = threadIdx.x;
    const int warp = t >> 5, lane = t & 31;
    const int lr = lane >> 2, lc = (lane & 3) * 2;
    const int wm = warp >> 1, wn = warp & 1;
    const int m0 = blockIdx.y * 128, n0 = blockIdx.x * 64;
    const int ar = t >> 1, acb = (t & 1) * 16;
    const int wr = t >> 2, wcb = (t & 3) * 8;
    const uint32_t sAh_b = smem_u32(sAh), sAl_b = smem_u32(sAl);
    const uint32_t sWh_b = smem_u32(sWh), sWl_b = smem_u32(sWl);

    const int row = m0 + ar;
    const int bidx = row >> 10, mm = row & 1023;
    const int pi = mm >> 5, pj = mm & 31;
    long pix[4];
#pragma unroll
    for (int qq = 0; qq < 4; qq++)
        pix[qq] = (long)bidx * (N_ * C_) +
                  (long)(((2 * pi + (qq >> 1)) * 64) + 2 * pj + (qq & 1)) * C_;

    float acc[2][4][4];
#pragma unroll
    for (int i = 0; i < 2; i++)
#pragma unroll
        for (int j = 0; j < 4; j++)
#pragma unroll
            for (int k = 0; k < 4; k++) acc[i][j][k] = 0.f;

    float4 pa[4];
    uint4 pwh, pwl;
    {
        const float* src = xp + pix[0] + acb;
#pragma unroll
        for (int j = 0; j < 4; j++) pa[j] = *(const float4*)(src + j * 4);
        const long wb = (long)(n0 + wr) * 1024 + wcb;
        pwh = *(const uint4*)(Wh + wb);
        pwl = *(const uint4*)(Wl + wb);
    }

    for (int k0 = 0; k0 < 1024; k0 += 32) {
        __syncthreads();
        split_store16(pa, &sAh[ar * GSTR + acb], &sAl[ar * GSTR + acb]);
        *(uint4*)&sWh[wr * GSTR + wcb] = pwh;
        *(uint4*)&sWl[wr * GSTR + wcb] = pwl;
        if (k0 + 32 < 1024) {
            const int kn = k0 + 32;
            const float* src = xp + pix[kn >> 8] + (kn & 255) + acb;
#pragma unroll
            for (int j = 0; j < 4; j++) pa[j] = *(const float4*)(src + j * 4);
            const long wb = (long)(n0 + wr) * 1024 + kn + wcb;
            pwh = *(const uint4*)(Wh + wb);
            pwl = *(const uint4*)(Wl + wb);
        }
        __syncthreads();
        gemm_tile_compute(sAh_b, sAl_b, sWh_b, sWl_b, acc, lane, wm, wn);
    }
    gemm_epilogue(acc, bias, Cp, 256, m0, n0, lr, lc, wm, wn);
}

// ---------------------------------------------------------------------------
// LayerNorm over C=256, writes bf16 hi/lo.
// ---------------------------------------------------------------------------
__global__ void __launch_bounds__(256)
ln_kernel(const float* __restrict__ xs,
          __nv_bfloat16* __restrict__ outh, __nv_bfloat16* __restrict__ outl,
          const float* __restrict__ w0, const float* __restrict__ b0,
          const float* __restrict__ w1, const float* __restrict__ b1)
{
    __shared__ float red[8];
    const int row = blockIdx.x;
    const int s = row >> 11;
    const float* w  = s ? w1 : w0;
    const float* bb = s ? b1 : b0;
    const float* p = xs + (long)row * C_;
    const int t = threadIdx.x;

    const float v = p[t];
    float x = v;
#pragma unroll
    for (int o = 16; o; o >>= 1) x += __shfl_xor_sync(0xffffffffu, x, o);
    if ((t & 31) == 0) red[t >> 5] = x;
    __syncthreads();
    float mu = 0.f;
#pragma unroll
    for (int i = 0; i < 8; i++) mu += red[i];
    mu *= (1.f / 256.f);
    __syncthreads();

    const float dv = v - mu;
    float sq = dv * dv;
#pragma unroll
    for (int o = 16; o; o >>= 1) sq += __shfl_xor_sync(0xffffffffu, sq, o);
    if ((t & 31) == 0) red[t >> 5] = sq;
    __syncthreads();
    float var = 0.f;
#pragma unroll
    for (int i = 0; i < 8; i++) var += red[i];
    var *= (1.f / 256.f);

    float y = dv * rsqrtf(var + 1e-5f) * w[t] + bb[t];
    __nv_bfloat16 hi = __float2bfloat16_rn(y);
    outh[(long)row * C_ + t] = hi;
    outl[(long)row * C_ + t] = __float2bfloat16_rn(y - __bfloat162float(hi));
}

// ---------------------------------------------------------------------------
// fp16 mma attention, centered softmax, ldmatrix frags, MMA-based row sums.
//   P' = exp(s) - 1 ;  out = (colsum_V + P' V) / (1024 + sum P')
// ---------------------------------------------------------------------------
#define KSTR 40   // fp16 row stride (32 + 8)
#define VSTR 72   // fp16 row stride (64 + 8)

__global__ void __launch_bounds__(256)
attn_f16_kernel(const float* __restrict__ q, const float* __restrict__ kv,
                const float* __restrict__ vcs,
                __nv_bfloat16* __restrict__ oh, __nv_bfloat16* __restrict__ ol)
{
    __shared__ __align__(16) __half qs[128 * KSTR];
    __shared__ __align__(16) __half ks[64 * KSTR];
    __shared__ __align__(16) __half vt[32 * VSTR];

    const int t = threadIdx.x;
    const int warp = t >> 5, lane = t & 31;
    const int lr = lane >> 2, lc = (lane & 3) * 2;
    const int arow = lane & 7, sel = lane >> 3;
    const int qrow0 = warp * 16;
    const uint32_t ks_b = smem_u32(ks), vt_b = smem_u32(vt);
    const uint32_t kboff = (uint32_t)(2 * ((arow + 8 * (sel >> 1)) * KSTR +
                                           8 * (sel & 1)));
    const uint32_t vboff = (uint32_t)(2 * ((arow + 8 * (sel >> 1)) * VSTR +
                                           8 * (sel & 1)));

    const int qt = blockIdx.x, bhid = blockIdx.y, s = blockIdx.z;
    const int h = bhid & 7;
    const long sb = (long)(s * 2 + (bhid >> 3));
    const float* qg  = q  + (sb * N_ + (long)qt * 128) * C_ + h * 32;
    const float* kvg = kv + sb * M_ * 512;

    // ---- stage Q (fp16, scaled) ----
#pragma unroll
    for (int i = 0; i < 16; i++) {
        int flat = t + i * 256;
        int rr = flat >> 5, d = flat & 31;
        qs[rr * KSTR + d] = __float2half_rn(qg[(long)rr * C_ + d] * ATTN_SCALE);
    }
    __syncthreads();

    uint32_t aQ[2][4];
#pragma unroll
    for (int kt = 0; kt < 2; kt++) {
        aQ[kt][0] = *(const uint32_t*)&qs[(qrow0 + lr) * KSTR + kt * 16 + lc];
        aQ[kt][1] = *(const uint32_t*)&qs[(qrow0 + lr + 8) * KSTR + kt * 16 + lc];
        aQ[kt][2] = *(const uint32_t*)&qs[(qrow0 + lr) * KSTR + kt * 16 + lc + 8];
        aQ[kt][3] = *(const uint32_t*)&qs[(qrow0 + lr + 8) * KSTR + kt * 16 + lc + 8];
    }

    float oacc[4][4];
#pragma unroll
    for (int i = 0; i < 4; i++)
#pragma unroll
        for (int j = 0; j < 4; j++) oacc[i][j] = 0.f;
    float sums[4] = {0.f, 0.f, 0.f, 0.f};
    const uint32_t bOnes[2] = {0x3C003C00u, 0x3C003C00u};  // fp16 1.0 x4

    // ---- prefetch chunk 0 into regs ----
    float pk[8], pv[8];
    {
        const float* kg = kvg + h * 32;
#pragma unroll
        for (int i = 0; i < 8; i++) {
            int flat = t + i * 256;
            int key = flat >> 5, d = flat & 31;
            pk[i] = kg[(long)key * 512 + d];
            pv[i] = kg[(long)key * 512 + 256 + d];
        }
    }

    for (int c = 0; c < 16; c++) {
        __syncthreads();
#pragma unroll
        for (int i = 0; i < 8; i++) {
            int flat = t + i * 256;
            int key = flat >> 5, d = flat & 31;
            ks[key * KSTR + d] = __float2half_rn(pk[i]);
            vt[d * VSTR + key] = __float2half_rn(pv[i]);
        }
        if (c < 15) {
            const float* kg = kvg + (long)((c + 1) * 64) * 512 + h * 32;
#pragma unroll
            for (int i = 0; i < 8; i++) {
                int flat = t + i * 256;
                int key = flat >> 5, d = flat & 31;
                pk[i] = kg[(long)key * 512 + d];
                pv[i] = kg[(long)key * 512 + 256 + d];
            }
        }
        __syncthreads();

        // ---- S = Q K^T (B frags via ldmatrix) ----
        float sc[8][4];
#pragma unroll
        for (int nt = 0; nt < 8; nt++)
            sc[nt][0] = sc[nt][1] = sc[nt][2] = sc[nt][3] = 0.f;
#pragma unroll
        for (int kt = 0; kt < 2; kt++) {
            uint32_t bK[8][2];
#pragma unroll
            for (int np = 0; np < 4; np++) {
                uint32_t off = kboff +
                    (uint32_t)(2 * ((np * 16) * KSTR + kt * 16));
                ldsm4(bK[np*2][0], bK[np*2][1], bK[np*2+1][0], bK[np*2+1][1],
                      ks_b + off);
            }
#pragma unroll
            for (int nt = 0; nt < 8; nt++)
                mma_f16(sc[nt], aQ[kt], bK[nt]);
        }

        // ---- P' = exp(S) - 1 ----
#pragma unroll
        for (int nt = 0; nt < 8; nt++) {
            sc[nt][0] = __expf(sc[nt][0]) - 1.f;
            sc[nt][1] = __expf(sc[nt][1]) - 1.f;
            sc[nt][2] = __expf(sc[nt][2]) - 1.f;
            sc[nt][3] = __expf(sc[nt][3]) - 1.f;
        }

        // ---- O += P' V ; row sums += P' * ones ----
#pragma unroll
        for (int kt = 0; kt < 4; kt++) {
            uint32_t aP[4];
            aP[0] = pack_h2(sc[kt * 2][0], sc[kt * 2][1]);
            aP[1] = pack_h2(sc[kt * 2][2], sc[kt * 2][3]);
            aP[2] = pack_h2(sc[kt * 2 + 1][0], sc[kt * 2 + 1][1]);
            aP[3] = pack_h2(sc[kt * 2 + 1][2], sc[kt * 2 + 1][3]);
            mma_f16(sums, aP, bOnes);
            uint32_t bV[4][2];
#pragma unroll
            for (int np = 0; np < 2; np++) {
                uint32_t off = vboff +
                    (uint32_t)(2 * ((np * 16) * VSTR + kt * 16));
                ldsm4(bV[np*2][0], bV[np*2][1], bV[np*2+1][0], bV[np*2+1][1],
                      vt_b + off);
            }
#pragma unroll
            for (int nt = 0; nt < 4; nt++)
                mma_f16(oacc[nt], aP, bV[nt]);
        }
    }

    // ---- finalize (sums[0]/sums[2] hold full row sums; all lanes agree) ----
    const float inv0 = 1.f / (1024.f + sums[0]);
    const float inv1 = 1.f / (1024.f + sums[2]);

    const long obase = (sb * N_ + (long)qt * 128 + qrow0) * C_ + h * 32;
#pragma unroll
    for (int nt = 0; nt < 4; nt++) {
        const int col = nt * 8 + lc;
        float cs0 = 0.f, cs1 = 0.f;
#pragma unroll
        for (int seg = 0; seg < 8; seg++) {
            cs0 += vcs[(sb * 8 + seg) * 256 + h * 32 + col];
            cs1 += vcs[(sb * 8 + seg) * 256 + h * 32 + col + 1];
        }
        float o00 = (cs0 + oacc[nt][0]) * inv0;
        float o01 = (cs1 + oacc[nt][1]) * inv0;
        float o10 = (cs0 + oacc[nt][2]) * inv1;
        float o11 = (cs1 + oacc[nt][3]) * inv1;
        long i0 = obase + (long)lr * C_ + col;
        long i1 = obase + (long)(lr + 8) * C_ + col;
        __nv_bfloat16 h00 = __float2bfloat16_rn(o00);
        __nv_bfloat16 h01 = __float2bfloat16_rn(o01);
        __nv_bfloat16 h10 = __float2bfloat16_rn(o10);
        __nv_bfloat16 h11 = __float2bfloat16_rn(o11);
        oh[i0] = h00; oh[i0 + 1] = h01;
        oh[i1] = h10; oh[i1 + 1] = h11;
        ol[i0]     = __float2bfloat16_rn(o00 - __bfloat162float(h00));
        ol[i0 + 1] = __float2bfloat16_rn(o01 - __bfloat162float(h01));
        ol[i1]     = __float2bfloat16_rn(o10 - __bfloat162float(h10));
        ol[i1 + 1] = __float2bfloat16_rn(o11 - __bfloat162float(h11));
    }
}

// ---------------------------------------------------------------------------
extern "C" void kernel_launch(void* const* d_in, const int* in_sizes, int n_in,
                              void* d_out, int out_size)
{
    const float* x0    = (const float*)d_in[0];
    const float* x1    = (const float*)d_in[1];
    const float* Wq    = (const float*)d_in[2];
    const float* Wkv   = (const float*)d_in[3];
    const float* Wproj = (const float*)d_in[4];
    const float* bproj = (const float*)d_in[5];
    const float* Wsr   = (const float*)d_in[6];
    const float* bsr   = (const float*)d_in[7];
    const float* lw0   = (const float*)d_in[8];
    const float* lb0   = (const float*)d_in[9];
    const float* lw1   = (const float*)d_in[10];
    const float* lb1   = (const float*)d_in[11];
    float* out = (float*)d_out;

    float *qp, *xsp, *kvp, *vcsp;
    __nv_bfloat16 *xsh, *xsl, *ohp, *olp;
    __nv_bfloat16 *wqh, *wql, *wkvh, *wkvl, *wph, *wpl, *wsrh, *wsrl;
    cudaGetSymbolAddress((void**)&qp,   g_q);
    cudaGetSymbolAddress((void**)&xsp,  g_xs);
    cudaGetSymbolAddress((void**)&kvp,  g_kv);
    cudaGetSymbolAddress((void**)&vcsp, g_vcs);
    cudaGetSymbolAddress((void**)&xsh,  g_xsh);
    cudaGetSymbolAddress((void**)&xsl,  g_xsl);
    cudaGetSymbolAddress((void**)&ohp,  g_oh);
    cudaGetSymbolAddress((void**)&olp,  g_ol);
    cudaGetSymbolAddress((void**)&wqh,  g_wqh);
    cudaGetSymbolAddress((void**)&wql,  g_wql);
    cudaGetSymbolAddress((void**)&wkvh, g_wkvh);
    cudaGetSymbolAddress((void**)&wkvl, g_wkvl);
    cudaGetSymbolAddress((void**)&wph,  g_wph);
    cudaGetSymbolAddress((void**)&wpl,  g_wpl);
    cudaGetSymbolAddress((void**)&wsrh, g_wsrh);
    cudaGetSymbolAddress((void**)&wsrl, g_wsrl);

    const long XSTR_ = (long)B_ * N_ * C_;   // 2,097,152
    const long SSTR_ = (long)B_ * M_ * C_;   // 524,288

    // 0) weight conversions (small)
    cvt_split_kernel<<<256, 256>>>(Wq, wqh, wql, 256 * 256);
    cvt_split_kernel<<<512, 256>>>(Wkv, wkvh, wkvl, 512 * 256);
    cvt_split_kernel<<<256, 256>>>(Wproj, wph, wpl, 256 * 256);
    wsr_perm_kernel<<<1024, 256>>>(Wsr, wsrh, wsrl);

    // 1) q = x @ Wq^T  (fp32 x, inline split, pipelined)
    gemm_x_kernel<<<dim3(4, 64, 2), 256>>>(x0, x1, wqh, wql, qp);
    // 2) spatial-reduction conv + bias (fp32 x, inline split, pipelined)
    conv_split_f32<<<dim3(4, 16, 2), 256>>>(x0, x1, wsrh, wsrl, bsr, xsp);
    // 3) layernorm -> bf16 hi/lo
    ln_kernel<<<NSTREAM * B_ * M_, 256>>>(xsp, xsh, xsl, lw0, lb0, lw1, lb1);
    // 4) kv = ln(xs) @ Wkv^T (pipelined)
    gemm_bf16_split<<<dim3(8, 16, 2), 256>>>(xsh, xsl, SSTR_, wkvh, wkvl,
                                             nullptr, kvp,
                                             (long)B_ * M_ * 2 * C_, 512, 256);
    // 5) V column sums
    vcs_kernel<<<dim3(8, 4), 256>>>(kvp, vcsp);
    // 6) fp16 attention (MMA row sums) -> bf16 hi/lo
    attn_f16_kernel<<<dim3(32, 16, 2), 256>>>(qp, kvp, vcsp, ohp, olp);
    // 7) out = attn @ Wproj^T + bproj (pipelined)
    gemm_bf16_split<<<dim3(4, 64, 2), 256>>>(ohp, olp, XSTR_, wph, wpl,
                                             bproj, out, XSTR_, 256, 256);
}